// round 12
// baseline (speedup 1.0000x reference)
#include <cuda_runtime.h>
#include <cuda_fp16.h>
#include <cstdint>

// Problem constants
#define NNODES 100000
#define NEDGES 500000
#define DZ     128
#define HID    512
#define NCOLS  1024     // [A | B] per node
#define OUTC   2
#define KTOT   128      // plain fp16 K

// Scratch (static device arrays: allocation-free per harness rules)
__device__ __half g_Ch[(size_t)NNODES * NCOLS];   // C = [A|B] in fp16 (205 MB)
__device__ __half g_A[(size_t)NNODES * KTOT];     // z in fp16 (25.6 MB)
__device__ __half g_B[(size_t)NCOLS  * KTOT];     // W1 reshaped, fp16 (256 KB)

__device__ __forceinline__ uint32_t smem_u32(const void* p) {
    uint32_t a;
    asm("{ .reg .u64 t; cvta.to.shared.u64 t, %1; cvt.u32.u64 %0, t; }"
        : "=r"(a) : "l"(p));
    return a;
}

__device__ __forceinline__ uint2 cvt4_fp16(float4 v) {
    uint16_t h[4];
    h[0] = __half_as_ushort(__float2half_rn(v.x));
    h[1] = __half_as_ushort(__float2half_rn(v.y));
    h[2] = __half_as_ushort(__float2half_rn(v.z));
    h[3] = __half_as_ushort(__float2half_rn(v.w));
    uint2 p;
    p.x = (uint32_t)h[0] | ((uint32_t)h[1] << 16);
    p.y = (uint32_t)h[2] | ((uint32_t)h[3] << 16);
    return p;
}

// ---------------------------------------------------------------------------
// Prep (merged): A-part converts z -> fp16 [NNODES,128];
// B-part reshapes W1 rows -> fp16 [NCOLS,128].
// ---------------------------------------------------------------------------
#define PREP_A_WORK (NNODES * 32)
#define PREP_B_WORK (NCOLS * 32)

__global__ __launch_bounds__(256)
void prep_kernel(const float* __restrict__ z, const float* __restrict__ W1) {
    int idx = blockIdx.x * blockDim.x + threadIdx.x;
    if (idx < PREP_A_WORK) {
        float4 v = __ldg(((const float4*)z) + idx);
        *(uint2*)(g_A + (size_t)idx * 4) = cvt4_fp16(v);
    } else if (idx < PREP_A_WORK + PREP_B_WORK) {
        int i2 = idx - PREP_A_WORK;
        int n = i2 >> 5;
        int c4 = i2 & 31;
        const float4* src = (n < HID)
            ? ((const float4*)W1 + n * 64 + c4)
            : ((const float4*)W1 + (n - HID) * 64 + 32 + c4);
        float4 v = __ldg(src);
        *(uint2*)(g_B + (size_t)n * KTOT + c4 * 4) = cvt4_fp16(v);
    }
}

// ---------------------------------------------------------------------------
// HMMA GEMM: C[M,1024] = A[M,128] @ B[1024,128]^T  (+ b1 on cols < 512),
// stored fp16. Tile 128x128x32, 256 threads (8 warps, each 64x32),
// mma.m16n8k16 fp16 (fp32 acc), 4-stage full-K cp.async prefetch,
// SMEM-staged coalesced epilogue.  (At legacy-HMMA throughput ceiling.)
// ---------------------------------------------------------------------------
#define BM 128
#define BN 128
#define BK 32
#define LDA 40            // smem row stride in halfs (conflict-free ldmatrix)
#define GSTAGE (BM * LDA) // halfs per operand stage = 5120
#define GEMM_SMEM (8 * GSTAGE * 2)   // 4 A-stages + 4 B-stages = 81920 B
#define EPI_LD 136        // epilogue staging row stride (halfs), conflict-free

__global__ __launch_bounds__(256, 2)
void gemm_hmma_kernel(const float* __restrict__ b1) {
    extern __shared__ __half gsm[];
    __half* As = gsm;                 // [4][GSTAGE]
    __half* Bs = gsm + 4 * GSTAGE;    // [4][GSTAGE]

    const int tid  = threadIdx.x;
    const int lane = tid & 31;
    const int wid  = tid >> 5;
    const int wm   = wid >> 2;       // 0..1 -> m offset wm*64
    const int wn   = wid & 3;        // 0..3 -> n offset wn*32
    const int bn   = blockIdx.x * BN;   // x = n-tile so concurrent CTAs share A
    const int bm   = blockIdx.y * BM;

    float acc[4][4][4];
    #pragma unroll
    for (int i = 0; i < 4; i++)
        #pragma unroll
        for (int j = 0; j < 4; j++)
            #pragma unroll
            for (int k = 0; k < 4; k++) acc[i][j][k] = 0.0f;

    const int a_r = lane & 15;
    const int a_k = (lane >> 4) * 8;
    const int b_r = (lane & 7) + (lane >> 4) * 8;
    const int b_k = ((lane >> 3) & 1) * 8;

    auto load_stage = [&](int it, int buf) {
        const int k0 = it * BK;
        #pragma unroll
        for (int j = 0; j < 2; j++) {
            int li  = tid + j * 256;      // 0..511 over 128 rows x 4 chunks
            int row = li >> 2;
            int ch  = (li & 3) * 8;
            uint32_t da = smem_u32(As + buf * GSTAGE + row * LDA + ch);
            const __half* sa = g_A + (size_t)(bm + row) * KTOT + k0 + ch;
            int sz = (bm + row < NNODES) ? 16 : 0;
            asm volatile("cp.async.cg.shared.global [%0], [%1], 16, %2;\n"
                         :: "r"(da), "l"(sa), "r"(sz));
            uint32_t db = smem_u32(Bs + buf * GSTAGE + row * LDA + ch);
            const __half* sb = g_B + (size_t)(bn + row) * KTOT + k0 + ch;
            asm volatile("cp.async.cg.shared.global [%0], [%1], 16;\n"
                         :: "r"(db), "l"(sb));
        }
        asm volatile("cp.async.commit_group;\n");
    };

    auto compute_stage = [&](int buf) {
        const __half* Ab = As + buf * GSTAGE;
        const __half* Bb = Bs + buf * GSTAGE;
        #pragma unroll
        for (int kk = 0; kk < BK; kk += 16) {
            uint32_t af[4][4], bf[2][4];
            #pragma unroll
            for (int mi = 0; mi < 4; mi++) {
                uint32_t addr = smem_u32(Ab + (wm * 64 + mi * 16 + a_r) * LDA + kk + a_k);
                asm volatile("ldmatrix.sync.aligned.m8n8.x4.shared.b16 {%0,%1,%2,%3}, [%4];"
                             : "=r"(af[mi][0]), "=r"(af[mi][1]),
                               "=r"(af[mi][2]), "=r"(af[mi][3]) : "r"(addr));
            }
            #pragma unroll
            for (int pi = 0; pi < 2; pi++) {
                uint32_t addr = smem_u32(Bb + (wn * 32 + pi * 16 + b_r) * LDA + kk + b_k);
                asm volatile("ldmatrix.sync.aligned.m8n8.x4.shared.b16 {%0,%1,%2,%3}, [%4];"
                             : "=r"(bf[pi][0]), "=r"(bf[pi][1]),
                               "=r"(bf[pi][2]), "=r"(bf[pi][3]) : "r"(addr));
            }
            #pragma unroll
            for (int mi = 0; mi < 4; mi++)
                #pragma unroll
                for (int nb = 0; nb < 4; nb++) {
                    uint32_t bb0 = bf[nb >> 1][(nb & 1) * 2];
                    uint32_t bb1 = bf[nb >> 1][(nb & 1) * 2 + 1];
                    asm volatile(
                        "mma.sync.aligned.m16n8k16.row.col.f32.f16.f16.f32 "
                        "{%0,%1,%2,%3}, {%4,%5,%6,%7}, {%8,%9}, {%0,%1,%2,%3};"
                        : "+f"(acc[mi][nb][0]), "+f"(acc[mi][nb][1]),
                          "+f"(acc[mi][nb][2]), "+f"(acc[mi][nb][3])
                        : "r"(af[mi][0]), "r"(af[mi][1]),
                          "r"(af[mi][2]), "r"(af[mi][3]),
                          "r"(bb0), "r"(bb1));
                }
        }
    };

    // full-K prefetch: issue 3 stages up front
    load_stage(0, 0);
    load_stage(1, 1);
    load_stage(2, 2);

    asm volatile("cp.async.wait_group 2;\n" ::: "memory");
    __syncthreads();
    load_stage(3, 3);
    compute_stage(0);

    asm volatile("cp.async.wait_group 2;\n" ::: "memory");
    __syncthreads();
    compute_stage(1);

    asm volatile("cp.async.wait_group 1;\n" ::: "memory");
    __syncthreads();
    compute_stage(2);

    asm volatile("cp.async.wait_group 0;\n" ::: "memory");
    __syncthreads();
    compute_stage(3);

    // ---- Epilogue: acc -> SMEM staging (fp16, +b1) -> coalesced stores ----
    __syncthreads();    // all reads of stage buffers complete before reuse
    __half* cst = gsm;  // [128][EPI_LD]
    const bool addb = (bn < HID);
    const int col0 = wn * 32;
    #pragma unroll
    for (int mi = 0; mi < 4; mi++) {
        #pragma unroll
        for (int nb = 0; nb < 4; nb++) {
            int r0 = wm * 64 + mi * 16 + (lane >> 2);
            int cl = col0 + nb * 8 + (lane & 3) * 2;
            float bx = addb ? __ldg(b1 + bn + cl)     : 0.0f;
            float by = addb ? __ldg(b1 + bn + cl + 1) : 0.0f;
            *(__half2*)(cst + r0 * EPI_LD + cl) =
                __floats2half2_rn(acc[mi][nb][0] + bx, acc[mi][nb][1] + by);
            *(__half2*)(cst + (r0 + 8) * EPI_LD + cl) =
                __floats2half2_rn(acc[mi][nb][2] + bx, acc[mi][nb][3] + by);
        }
    }
    __syncthreads();
    // copy-out: 128 rows x 256B, 16B per thread-chunk, fully coalesced
    #pragma unroll
    for (int i = tid; i < 128 * 16; i += 256) {
        int row = i >> 4;
        int j   = i & 15;
        if (bm + row < NNODES) {
            uint4 v = *(const uint4*)(cst + row * EPI_LD + j * 8);
            *(uint4*)(g_Ch + (size_t)(bm + row) * NCOLS + bn + j * 8) = v;
        }
    }
}

// ---------------------------------------------------------------------------
// Edge kernel (mma): 16-edge tiles. CTA = 256 threads (8 warps).
// Stage = 16 A-rows + 16 B-rows (1KB each, row stride 1040B for conflict-free
// fragment builds), 2-stage cp.async pipeline. Each warp computes a 64-wide
// k-slice with 4x mma.m16n8k16 (A-fragments = relu(A+B) built from SMEM,
// B = W2 fragment table, n=2..7 zero-padded). Cross-warp SMEM reduction.
// ---------------------------------------------------------------------------
#define EMMA_THREADS 256
#define EMMA_BLOCKS  296
#define NTILES (NEDGES / 16)       // 31250 exact
#define ROWB   1040                // staged row stride (4-bank rotation/row)
#define STAGEB (32 * ROWB)         // 33280 B
#define EMMA_SMEM (12288 + 2 * STAGEB)   // sWf 8K + sRed 4K + stages = 78848

__global__ __launch_bounds__(EMMA_THREADS, 2)
void edge_mma_kernel(const int* __restrict__ batch_r,
                     const int* __restrict__ batch_c,
                     const float* __restrict__ W2,
                     const float* __restrict__ b2,
                     float* __restrict__ out) {
    extern __shared__ char esm[];
    uint2  (*sWf)[32]  = (uint2  (*)[32])esm;            // [kstep 32][lane 32]
    float4 (*sRed)[32] = (float4 (*)[32])(esm + 8192);   // [warp 8][lane 32]
    char* stage = esm + 12288;                            // [2][32][ROWB]

    const int tid  = threadIdx.x;
    const int w    = tid >> 5;
    const int lane = tid & 31;
    const int G    = EMMA_BLOCKS;

    auto issue = [&](int tile, int b) {
        if (tile < NTILES) {
            int row = tid >> 3;          // 0..31
            int seg = tid & 7;
            int e = tile * 16 + (row & 15);
            const char* src;
            if (row < 16)
                src = (const char*)g_Ch + (size_t)__ldg(batch_r + e) * 2048;
            else
                src = (const char*)g_Ch + (size_t)__ldg(batch_c + e) * 2048 + 1024;
            uint32_t d = smem_u32(stage + b * STAGEB + row * ROWB + seg * 16);
            src += seg * 16;
            // chunk = seg + 8*j: per j a warp covers 4 rows x contiguous 128B
            #pragma unroll
            for (int j = 0; j < 8; j++)
                asm volatile("cp.async.cg.shared.global [%0], [%1], 16;\n"
                             :: "r"(d + j * 128), "l"(src + j * 128));
        }
        asm volatile("cp.async.commit_group;\n");
    };

    const int t0 = blockIdx.x;
    issue(t0, 0);
    issue(t0 + G, 1);

    // Build W2 fragment table (n8k16 col-major B-frags; n>=2 zeroed)
    #pragma unroll
    for (int p = 0; p < 4; p++) {
        int idx = tid + p * 256;
        int kstep = idx >> 5;
        int l = idx & 31;
        int n = l >> 2;
        int k0 = kstep * 16 + (l & 3) * 2;
        __half z = __float2half_rn(0.f);
        __half h00 = (n < 2) ? __float2half_rn(__ldg(W2 + n * HID + k0))     : z;
        __half h01 = (n < 2) ? __float2half_rn(__ldg(W2 + n * HID + k0 + 1)) : z;
        __half h10 = (n < 2) ? __float2half_rn(__ldg(W2 + n * HID + k0 + 8)) : z;
        __half h11 = (n < 2) ? __float2half_rn(__ldg(W2 + n * HID + k0 + 9)) : z;
        __half2 b0 = __halves2half2(h00, h01);
        __half2 b1 = __halves2half2(h10, h11);
        uint2 u;
        u.x = *(uint32_t*)&b0;
        u.y = *(uint32_t*)&b1;
        sWf[kstep][l] = u;
    }
    const float bb0 = __ldg(b2);
    const float bb1 = __ldg(b2 + 1);
    __syncthreads();

    const __half2 zero2 = __float2half2_rn(0.0f);
    int k = 0;
    for (int t = t0; t < NTILES; t += G, k ^= 1) {
        asm volatile("cp.async.wait_group 1;\n" ::: "memory");
        __syncthreads();     // stage k fully landed for ALL threads

        // ---- compute: warp w owns ksteps w*4 .. w*4+3 (k-cols w*64..+63) ----
        {
            const char* st = stage + k * STAGEB;
            const int i   = lane >> 2;
            const int kkb = (lane & 3) * 4;     // byte offset of k-pair in step
            const char* rA0 = st + i * ROWB;
            const char* rA8 = st + (i + 8) * ROWB;
            const char* rB0 = st + (16 + i) * ROWB;
            const char* rB8 = st + (24 + i) * ROWB;
            float c0 = 0.f, c1 = 0.f, c2 = 0.f, c3 = 0.f;
            #pragma unroll
            for (int j = 0; j < 4; j++) {
                const int kb = (w * 4 + j) * 32 + kkb;
                __half2 h;
                uint32_t a0, a1, a2, a3;
                h = __hmax2(__hadd2(*(const __half2*)(rA0 + kb),
                                    *(const __half2*)(rB0 + kb)), zero2);
                a0 = *(uint32_t*)&h;
                h = __hmax2(__hadd2(*(const __half2*)(rA8 + kb),
                                    *(const __half2*)(rB8 + kb)), zero2);
                a1 = *(uint32_t*)&h;
                h = __hmax2(__hadd2(*(const __half2*)(rA0 + kb + 16),
                                    *(const __half2*)(rB0 + kb + 16)), zero2);
                a2 = *(uint32_t*)&h;
                h = __hmax2(__hadd2(*(const __half2*)(rA8 + kb + 16),
                                    *(const __half2*)(rB8 + kb + 16)), zero2);
                a3 = *(uint32_t*)&h;
                uint2 bf = sWf[w * 4 + j][lane];
                asm volatile(
                    "mma.sync.aligned.m16n8k16.row.col.f32.f16.f16.f32 "
                    "{%0,%1,%2,%3}, {%4,%5,%6,%7}, {%8,%9}, {%0,%1,%2,%3};"
                    : "+f"(c0), "+f"(c1), "+f"(c2), "+f"(c3)
                    : "r"(a0), "r"(a1), "r"(a2), "r"(a3), "r"(bf.x), "r"(bf.y));
            }
            sRed[w][lane] = make_float4(c0, c1, c2, c3);
        }
        __syncthreads();     // sRed complete; stage k free for refill

        issue(t + 2 * G, k);

        // ---- cross-warp reduction + store (warp 0) ----
        if (tid < 32) {
            float4 f = sRed[0][lane];
            #pragma unroll
            for (int ww = 1; ww < 8; ww++) {
                float4 g = sRed[ww][lane];
                f.x += g.x; f.y += g.y; f.z += g.z; f.w += g.w;
            }
            if ((lane & 3) == 0) {     // these lanes hold cols 0,1
                int i = lane >> 2;
                size_t e0 = (size_t)t * 16 + i;
                float2 o;
                o.x = f.x + bb0; o.y = f.y + bb1;
                *(float2*)(out + 2 * e0) = o;          // edge i (row i)
                o.x = f.z + bb0; o.y = f.w + bb1;
                *(float2*)(out + 2 * (e0 + 8)) = o;    // edge i+8 (row i+8)
            }
        }
        // next-iteration __syncthreads orders reduce vs. sRed rewrite
    }
}

// ---------------------------------------------------------------------------
// Launch
// ---------------------------------------------------------------------------
extern "C" void kernel_launch(void* const* d_in, const int* in_sizes, int n_in,
                              void* d_out, int out_size) {
    const float* z       = (const float*)d_in[0];
    const int*   batch_r = (const int*)  d_in[1];
    const int*   batch_c = (const int*)  d_in[2];
    const float* W1      = (const float*)d_in[3];
    const float* b1      = (const float*)d_in[4];
    const float* W2      = (const float*)d_in[5];
    const float* b2      = (const float*)d_in[6];
    float* out = (float*)d_out;

    // Idempotent, capture-safe host-side attributes.
    cudaFuncSetAttribute(gemm_hmma_kernel,
                         cudaFuncAttributeMaxDynamicSharedMemorySize, GEMM_SMEM);
    cudaFuncSetAttribute(edge_mma_kernel,
                         cudaFuncAttributeMaxDynamicSharedMemorySize, EMMA_SMEM);

    // 1) fp16 operand prep (merged A+B)
    prep_kernel<<<(PREP_A_WORK + PREP_B_WORK + 255) / 256, 256>>>(z, W1);

    // 2) C = A @ B^T (+b1), fp16 out
    dim3 ggrid(NCOLS / BN, (NNODES + BM - 1) / BM);
    gemm_hmma_kernel<<<ggrid, 256, GEMM_SMEM>>>(b1);

    // 3) Edge decode: 16-edge mma tiles
    edge_mma_kernel<<<EMMA_BLOCKS, EMMA_THREADS, EMMA_SMEM>>>(
        batch_r, batch_c, W2, b2, out);
}